// round 9
// baseline (speedup 1.0000x reference)
#include <cuda_runtime.h>
#include <math.h>

// Problem constants
#define BQ 4
#define SQ 2048
#define DQ 1024
#define MROWS (BQ*SQ)          // 8192
#define NCH 8
#define CH (SQ/NCH)            // 256
#define NCTA 128
#define TPB 256

typedef unsigned long long ull;

// ---------------- scratch (static __device__, no allocations) ----------------
__device__ float g_retained[MROWS*DQ];
__device__ float g_inp[MROWS*DQ];
__device__ float g_gate[MROWS*DQ];
__device__ float g_bm[MROWS*DQ];
__device__ float g_states[MROWS*DQ];
__device__ float g_E[NCH*BQ*DQ];
__device__ float g_Cr[NCH*BQ*DQ];
// tagged mailbox: each word = (step_tag<<32) | float_bits, double buffered
__device__ ull g_ptag[2][NCTA][32];

__global__ void reset_bar() {
    int i = blockIdx.x * blockDim.x + threadIdx.x;   // 2*NCTA*32 = 8192 words
    ((ull*)g_ptag)[i] = 0ull;
}

// packed fp32x2 helpers (Blackwell FFMA2 via PTX)
__device__ __forceinline__ ull ffma2(ull a, ull b, ull c) {
    ull d;
    asm("fma.rn.f32x2 %0, %1, %2, %3;" : "=l"(d) : "l"(a), "l"(b), "l"(c));
    return d;
}
__device__ __forceinline__ void unpack2(ull v, float& lo, float& hi) {
    asm("mov.b64 {%0, %1}, %2;" : "=f"(lo), "=f"(hi) : "l"(v));
}
__device__ __forceinline__ ull ldrelax(const ull* p) {
    ull v;
    asm volatile("ld.relaxed.gpu.global.u64 %0, [%1];" : "=l"(v) : "l"(p) : "memory");
    return v;
}
__device__ __forceinline__ void strelax(ull* p, ull v) {
    asm volatile("st.relaxed.gpu.global.u64 [%0], %1;" :: "l"(p), "l"(v) : "memory");
}
// fast tanh: 1 - 2/(1 + 2^(2x*log2e));  ex2.approx + rcp.approx, err ~1e-7
__device__ __forceinline__ float tanh_fast(float x) {
    float e, r;
    asm("ex2.approx.f32 %0, %1;" : "=f"(e) : "f"(x * 2.8853900817779268f));
    asm("rcp.approx.f32 %0, %1;" : "=f"(r) : "f"(e + 1.0f));
    return fmaf(-2.0f, r, 1.0f);
}

// ---------------- retention scan (r = dec*r + k*v; retained = q*r) ----------
__global__ __launch_bounds__(TPB) void ret_pass1(const float* __restrict__ K_,
                                                 const float* __restrict__ V_,
                                                 const float* __restrict__ decay) {
    int gid = blockIdx.x * TPB + threadIdx.x;
    int d = gid & (DQ - 1);
    int t2 = gid >> 10;
    int b = t2 & (BQ - 1);
    int c = t2 >> 2;
    float dec = decay[d >> 6];
    long base = ((long)(b * SQ + c * CH)) * DQ + d;
    float E = 0.f;
#pragma unroll 4
    for (int i = 0; i < CH; ++i) {
        E = fmaf(dec, E, K_[base] * V_[base]);
        base += DQ;
    }
    g_E[(c * BQ + b) * DQ + d] = E;
}

__global__ __launch_bounds__(TPB) void ret_pass2(const float* __restrict__ decay) {
    int gid = blockIdx.x * TPB + threadIdx.x;
    int d = gid & (DQ - 1);
    int b = gid >> 10;
    float dec = decay[d >> 6];
    float p = dec;
#pragma unroll
    for (int i = 0; i < 8; ++i) p = p * p;        // dec^256
    float carry = 0.f;
    for (int c = 0; c < NCH; ++c) {
        int idx = (c * BQ + b) * DQ + d;
        g_Cr[idx] = carry;
        carry = fmaf(p, carry, g_E[idx]);
    }
}

__global__ __launch_bounds__(TPB) void ret_pass3(const float* __restrict__ Q_,
                                                 const float* __restrict__ K_,
                                                 const float* __restrict__ V_,
                                                 const float* __restrict__ decay) {
    int gid = blockIdx.x * TPB + threadIdx.x;
    int d = gid & (DQ - 1);
    int t2 = gid >> 10;
    int b = t2 & (BQ - 1);
    int c = t2 >> 2;
    float dec = decay[d >> 6];
    float r = g_Cr[(c * BQ + b) * DQ + d];
    long base = ((long)(b * SQ + c * CH)) * DQ + d;
#pragma unroll 4
    for (int i = 0; i < CH; ++i) {
        r = fmaf(dec, r, K_[base] * V_[base]);
        g_retained[base] = Q_[base] * r;
        base += DQ;
    }
}

// ---------------- big fp32 GEMM: C = X @ W^T + bias (opt sigmoid) -----------
__global__ __launch_bounds__(256) void gemm_nt(const float* __restrict__ X,
                                               const float* __restrict__ W,
                                               const float* __restrict__ bias,
                                               float* __restrict__ C,
                                               int M, int N, int K, int act) {
    __shared__ float Xs[16][132];
    __shared__ float Ws[16][132];
    const int tid = threadIdx.x;
    const int row0 = blockIdx.y * 128;
    const int col0 = blockIdx.x * 128;
    const int tx = tid & 15, ty = tid >> 4;
    const int lr = tid >> 2, lc = (tid & 3) << 2;
    const float* Xp = X + (long)(row0 + lr) * K + lc;
    const float* Wp = W + (long)(col0 + lr) * K + lc;
    float acc[8][8] = {};
    for (int k0 = 0; k0 < K; k0 += 16) {
        float4 xa = *(const float4*)(Xp + k0);
        float4 xb = *(const float4*)(Xp + 64L * K + k0);
        float4 wa = *(const float4*)(Wp + k0);
        float4 wb = *(const float4*)(Wp + 64L * K + k0);
        __syncthreads();
        Xs[lc + 0][lr] = xa.x; Xs[lc + 1][lr] = xa.y; Xs[lc + 2][lr] = xa.z; Xs[lc + 3][lr] = xa.w;
        Xs[lc + 0][lr + 64] = xb.x; Xs[lc + 1][lr + 64] = xb.y; Xs[lc + 2][lr + 64] = xb.z; Xs[lc + 3][lr + 64] = xb.w;
        Ws[lc + 0][lr] = wa.x; Ws[lc + 1][lr] = wa.y; Ws[lc + 2][lr] = wa.z; Ws[lc + 3][lr] = wa.w;
        Ws[lc + 0][lr + 64] = wb.x; Ws[lc + 1][lr + 64] = wb.y; Ws[lc + 2][lr + 64] = wb.z; Ws[lc + 3][lr + 64] = wb.w;
        __syncthreads();
#pragma unroll
        for (int kk = 0; kk < 16; ++kk) {
            float a[8], br[8];
            *(float4*)(a)     = *(const float4*)&Xs[kk][ty * 8];
            *(float4*)(a + 4) = *(const float4*)&Xs[kk][ty * 8 + 4];
            *(float4*)(br)     = *(const float4*)&Ws[kk][tx * 8];
            *(float4*)(br + 4) = *(const float4*)&Ws[kk][tx * 8 + 4];
#pragma unroll
            for (int i = 0; i < 8; ++i)
#pragma unroll
                for (int jj = 0; jj < 8; ++jj)
                    acc[i][jj] = fmaf(a[i], br[jj], acc[i][jj]);
        }
    }
    float bj[8];
#pragma unroll
    for (int jj = 0; jj < 8; ++jj) bj[jj] = bias ? bias[col0 + tx * 8 + jj] : 0.f;
#pragma unroll
    for (int i = 0; i < 8; ++i) {
        long row = row0 + ty * 8 + i;
        float o[8];
#pragma unroll
        for (int jj = 0; jj < 8; ++jj) {
            float v = acc[i][jj] + bj[jj];
            if (act) v = 1.f / (1.f + expf(-v));
            o[jj] = v;
        }
        *(float4*)&C[row * N + col0 + tx * 8]     = make_float4(o[0], o[1], o[2], o[3]);
        *(float4*)&C[row * N + col0 + tx * 8 + 4] = make_float4(o[4], o[5], o[6], o[7]);
    }
}

// ---------------- persistent sequential scan (the A GEMM recurrence) --------
// Mailbox where every u64 word self-tags its step: poll == fetch (one L2 hop,
// all relaxed, no fences). Software-pipelined polls (2 sets in flight) cut the
// miss granularity to ~120 cyc. A slice in registers; GEMV via broadcast LDS.
__global__ __launch_bounds__(TPB, 1) void scan_kernel(const float* __restrict__ A) {
    __shared__ float bl[4 * 1028];          // blended, 4 batches x 1028 (padded)
    __shared__ float part[2][256];          // parity-split warp partials
    const int tid = threadIdx.x, w = tid >> 5, lane = tid & 31;
    const int cta = blockIdx.x;
    const int c0 = cta * 8;
    const int j = lane >> 2, q = lane & 3, b = lane & 3;
    const int colg = c0 + j;
    const int slot = b * 8 + j;             // position in payload line

    // A slice -> registers (once)
    ull a2[16];
    {
        const float* Arow = A + (long)(c0 + j) * DQ + 128 * w + 4 * q;
#pragma unroll
        for (int i = 0; i < 8; ++i) {
            float4 t = *(const float4*)(Arow + 16 * i);
            a2[2 * i]     = ((const ull*)&t)[0];
            a2[2 * i + 1] = ((const ull*)&t)[1];
        }
    }

    float st = 0.f, gv = 0.f, iv = 0.f, mv = 0.f, gv_n = 0.f, iv_n = 0.f, mv_n = 0.f;
    if (w == 0) {
        long off = (long)(b * SQ) * DQ + colg;
        gv = g_gate[off]; iv = g_inp[off]; mv = g_bm[off];
        if (SQ > 1) {
            long off1 = ((long)b * SQ + 1) * DQ + colg;
            gv_n = g_gate[off1]; iv_n = g_inp[off1]; mv_n = g_bm[off1];
        }
        // preamble: publish blend_0 (st = 0) with tag 1 into parity 0
        float blv = fmaf(gv, st - iv, iv);
        strelax(&g_ptag[0][cta][slot], (1ull << 32) | (unsigned)__float_as_int(blv));
    }
    __syncthreads();

    // consumer mapping: lane covers source s = 16w + (lane>>1), words
    // [16*(lane&1), +16): b in {2h, 2h+1}, j = 0..7. One 128B gather per lane.
    const int s_src = 16 * w + (lane >> 1);
    const int half = lane & 1;
    const int src8 = s_src * 8;

    for (int t = 0; t < SQ; ++t) {
        const int p = t & 1;
        const ull thr = ((ull)(unsigned)(t + 1)) << 32;
        const ull* src = &g_ptag[p][s_src][16 * half];

        // ---- pipelined tagged poll: data arrives with the passing check ----
        ull Av[16], Bv[16];
#pragma unroll
        for (int i = 0; i < 16; ++i) Av[i] = ldrelax(src + i);
        bool useA;
        for (;;) {
#pragma unroll
            for (int i = 0; i < 16; ++i) Bv[i] = ldrelax(src + i);
            bool c = true;
#pragma unroll
            for (int i = 0; i < 16; ++i) c &= (Av[i] >= thr);
            if (__all_sync(0xffffffffu, c)) { useA = true; break; }
#pragma unroll
            for (int i = 0; i < 16; ++i) Av[i] = ldrelax(src + i);
            c = true;
#pragma unroll
            for (int i = 0; i < 16; ++i) c &= (Bv[i] >= thr);
            if (__all_sync(0xffffffffu, c)) { useA = false; break; }
        }

        // ---- stage the passing set's 16 floats into bl ----
        {
            float f[16];
#pragma unroll
            for (int i = 0; i < 16; ++i)
                f[i] = __int_as_float((int)(unsigned)(useA ? Av[i] : Bv[i]));
            const int b0 = 2 * half, b1 = b0 + 1;
            *(float4*)(bl + b0 * 1028 + src8)     = make_float4(f[0], f[1], f[2], f[3]);
            *(float4*)(bl + b0 * 1028 + src8 + 4) = make_float4(f[4], f[5], f[6], f[7]);
            *(float4*)(bl + b1 * 1028 + src8)     = make_float4(f[8], f[9], f[10], f[11]);
            *(float4*)(bl + b1 * 1028 + src8 + 4) = make_float4(f[12], f[13], f[14], f[15]);
        }
        __syncwarp();

        // ---- GEMV: A from regs, bl from SMEM (broadcast, conflict-free) ----
        float accb[4];
        const float* blw = bl + 128 * w + 4 * q;
#pragma unroll
        for (int b2 = 0; b2 < 4; ++b2) {
            ull acc0 = 0ull, acc1 = 0ull;
            const float* bp = blw + b2 * 1028;
#pragma unroll
            for (int i = 0; i < 8; ++i) {
                const ull* bp2 = (const ull*)(bp + 16 * i);
                acc0 = ffma2(a2[2 * i],     bp2[0], acc0);
                acc1 = ffma2(a2[2 * i + 1], bp2[1], acc1);
            }
            float l0, h0, l1, h1;
            unpack2(acc0, l0, h0);
            unpack2(acc1, l1, h1);
            accb[b2] = (l0 + h0) + (l1 + h1);
        }
        // butterfly over q bits: lane ends with the sum for batch b = q
        {
            float s0 = (q & 1) ? accb[0] : accb[1];
            float s2 = (q & 1) ? accb[2] : accb[3];
            float t0 = __shfl_xor_sync(0xffffffffu, s0, 1);
            float t2 = __shfl_xor_sync(0xffffffffu, s2, 1);
            float u0 = ((q & 1) ? accb[1] : accb[0]) + t0;  // b = q&1
            float u2 = ((q & 1) ? accb[3] : accb[2]) + t2;  // b = (q&1)+2
            float s  = (q & 2) ? u0 : u2;
            float r  = __shfl_xor_sync(0xffffffffu, s, 2);
            part[p][w * 32 + lane] = ((q & 2) ? u2 : u0) + r;
        }
        __syncthreads();

        // ---- reduce + tanh + publish next blend (warp0 only) ----
        if (w == 0) {
            float ssum = 0.f;
#pragma unroll
            for (int q8 = 0; q8 < 8; ++q8) ssum += part[p][q8 * 32 + lane];
            st = tanh_fast(ssum + mv);
            gv = gv_n; iv = iv_n; mv = mv_n;
            if (t + 1 < SQ) {
                float blv = fmaf(gv, st - iv, iv);
                strelax(&g_ptag[(t + 1) & 1][cta][slot],
                        (((ull)(unsigned)(t + 2)) << 32) | (unsigned)__float_as_int(blv));
            }
            g_states[((long)b * SQ + t) * DQ + colg] = st;
            if (t + 2 < SQ) {
                long off = ((long)b * SQ + (t + 2)) * DQ + colg;
                gv_n = g_gate[off]; iv_n = g_inp[off]; mv_n = g_bm[off];
            }
        }
    }
}

// ---------------- launch ----------------------------------------------------
extern "C" void kernel_launch(void* const* d_in, const int* in_sizes, int n_in,
                              void* d_out, int out_size) {
    const float* q     = (const float*)d_in[0];
    const float* k     = (const float*)d_in[1];
    const float* v     = (const float*)d_in[2];
    const float* Wi    = (const float*)d_in[3];
    const float* bi    = (const float*)d_in[4];
    const float* Wg    = (const float*)d_in[5];
    const float* bg    = (const float*)d_in[6];
    const float* A     = (const float*)d_in[7];
    const float* Bm    = (const float*)d_in[8];
    const float* Wo    = (const float*)d_in[9];
    const float* bo    = (const float*)d_in[10];
    const float* decay = (const float*)d_in[11];
    float* out = (float*)d_out;

    float *retained, *inp, *gate, *bm, *states;
    cudaGetSymbolAddress((void**)&retained, g_retained);
    cudaGetSymbolAddress((void**)&inp, g_inp);
    cudaGetSymbolAddress((void**)&gate, g_gate);
    cudaGetSymbolAddress((void**)&bm, g_bm);
    cudaGetSymbolAddress((void**)&states, g_states);

    // 1) retention prefix scan -> retained
    ret_pass1<<<(NCH * BQ * DQ) / TPB, TPB>>>(k, v, decay);
    ret_pass2<<<(BQ * DQ) / TPB, TPB>>>(decay);
    ret_pass3<<<(NCH * BQ * DQ) / TPB, TPB>>>(q, k, v, decay);

    // 2) parallel big GEMMs
    dim3 gg(DQ / 128, MROWS / 128);
    gemm_nt<<<gg, 256>>>(retained, Wi, bi, inp, MROWS, DQ, DQ, 0);
    gemm_nt<<<gg, 256>>>(inp, Wg, bg, gate, MROWS, DQ, DQ, 1);
    gemm_nt<<<gg, 256>>>(inp, Bm, (const float*)nullptr, bm, MROWS, DQ, DQ, 0);

    // 3) sequential state recurrence (tagged mailbox, pipelined polls)
    reset_bar<<<32, 256>>>();
    scan_kernel<<<NCTA, TPB>>>(A);

    // 4) output projection
    gemm_nt<<<gg, 256>>>(states, Wo, bo, out, MROWS, DQ, DQ, 0);
}

// round 11
// speedup vs baseline: 3.7074x; 3.7074x over previous
#include <cuda_runtime.h>
#include <math.h>

// Problem constants
#define BQ 4
#define SQ 2048
#define DQ 1024
#define MROWS (BQ*SQ)          // 8192
#define NCH 8
#define CH (SQ/NCH)            // 256
#define NCTA 128
#define TPB 256

typedef unsigned long long ull;

// ---------------- scratch (static __device__, no allocations) ----------------
__device__ float g_retained[MROWS*DQ];
__device__ float g_inp[MROWS*DQ];
__device__ float g_gate[MROWS*DQ];
__device__ float g_bm[MROWS*DQ];
__device__ float g_states[MROWS*DQ];
__device__ float g_E[NCH*BQ*DQ];
__device__ float g_Cr[NCH*BQ*DQ];
// mailbox: per-source payload (32 floats = 128B line), double buffered, + tag
__device__ float g_pay[2][NCTA][32];
__device__ unsigned g_tag[NCTA][32];   // one 128B line per source, word 0 used

__global__ void reset_bar() { g_tag[blockIdx.x][threadIdx.x] = 0u; }

// packed fp32x2 helpers (Blackwell FFMA2 via PTX)
__device__ __forceinline__ ull ffma2(ull a, ull b, ull c) {
    ull d;
    asm("fma.rn.f32x2 %0, %1, %2, %3;" : "=l"(d) : "l"(a), "l"(b), "l"(c));
    return d;
}
__device__ __forceinline__ void unpack2(ull v, float& lo, float& hi) {
    asm("mov.b64 {%0, %1}, %2;" : "=f"(lo), "=f"(hi) : "l"(v));
}
// fast tanh: 1 - 2/(1 + 2^(2x*log2e));  ex2.approx + rcp.approx, err ~1e-7
__device__ __forceinline__ float tanh_fast(float x) {
    float e, r;
    asm("ex2.approx.f32 %0, %1;" : "=f"(e) : "f"(x * 2.8853900817779268f));
    asm("rcp.approx.f32 %0, %1;" : "=f"(r) : "f"(e + 1.0f));
    return fmaf(-2.0f, r, 1.0f);
}

// ---------------- retention scan (r = dec*r + k*v; retained = q*r) ----------
__global__ __launch_bounds__(TPB) void ret_pass1(const float* __restrict__ K_,
                                                 const float* __restrict__ V_,
                                                 const float* __restrict__ decay) {
    int gid = blockIdx.x * TPB + threadIdx.x;
    int d = gid & (DQ - 1);
    int t2 = gid >> 10;
    int b = t2 & (BQ - 1);
    int c = t2 >> 2;
    float dec = decay[d >> 6];
    long base = ((long)(b * SQ + c * CH)) * DQ + d;
    float E = 0.f;
#pragma unroll 4
    for (int i = 0; i < CH; ++i) {
        E = fmaf(dec, E, K_[base] * V_[base]);
        base += DQ;
    }
    g_E[(c * BQ + b) * DQ + d] = E;
}

__global__ __launch_bounds__(TPB) void ret_pass2(const float* __restrict__ decay) {
    int gid = blockIdx.x * TPB + threadIdx.x;
    int d = gid & (DQ - 1);
    int b = gid >> 10;
    float dec = decay[d >> 6];
    float p = dec;
#pragma unroll
    for (int i = 0; i < 8; ++i) p = p * p;        // dec^256
    float carry = 0.f;
    for (int c = 0; c < NCH; ++c) {
        int idx = (c * BQ + b) * DQ + d;
        g_Cr[idx] = carry;
        carry = fmaf(p, carry, g_E[idx]);
    }
}

__global__ __launch_bounds__(TPB) void ret_pass3(const float* __restrict__ Q_,
                                                 const float* __restrict__ K_,
                                                 const float* __restrict__ V_,
                                                 const float* __restrict__ decay) {
    int gid = blockIdx.x * TPB + threadIdx.x;
    int d = gid & (DQ - 1);
    int t2 = gid >> 10;
    int b = t2 & (BQ - 1);
    int c = t2 >> 2;
    float dec = decay[d >> 6];
    float r = g_Cr[(c * BQ + b) * DQ + d];
    long base = ((long)(b * SQ + c * CH)) * DQ + d;
#pragma unroll 4
    for (int i = 0; i < CH; ++i) {
        r = fmaf(dec, r, K_[base] * V_[base]);
        g_retained[base] = Q_[base] * r;
        base += DQ;
    }
}

// ---------------- big fp32 GEMM: C = X @ W^T + bias (opt sigmoid) -----------
// 2 CTAs/SM forced for latency hiding (occ was 24%, issue 68%).
__global__ __launch_bounds__(256, 2) void gemm_nt(const float* __restrict__ X,
                                                  const float* __restrict__ W,
                                                  const float* __restrict__ bias,
                                                  float* __restrict__ C,
                                                  int M, int N, int K, int act) {
    __shared__ float Xs[16][132];
    __shared__ float Ws[16][132];
    const int tid = threadIdx.x;
    const int row0 = blockIdx.y * 128;
    const int col0 = blockIdx.x * 128;
    const int tx = tid & 15, ty = tid >> 4;
    const int lr = tid >> 2, lc = (tid & 3) << 2;
    const float* Xp = X + (long)(row0 + lr) * K + lc;
    const float* Wp = W + (long)(col0 + lr) * K + lc;
    float acc[8][8] = {};
    for (int k0 = 0; k0 < K; k0 += 16) {
        float4 xa = *(const float4*)(Xp + k0);
        float4 xb = *(const float4*)(Xp + 64L * K + k0);
        float4 wa = *(const float4*)(Wp + k0);
        float4 wb = *(const float4*)(Wp + 64L * K + k0);
        __syncthreads();
        Xs[lc + 0][lr] = xa.x; Xs[lc + 1][lr] = xa.y; Xs[lc + 2][lr] = xa.z; Xs[lc + 3][lr] = xa.w;
        Xs[lc + 0][lr + 64] = xb.x; Xs[lc + 1][lr + 64] = xb.y; Xs[lc + 2][lr + 64] = xb.z; Xs[lc + 3][lr + 64] = xb.w;
        Ws[lc + 0][lr] = wa.x; Ws[lc + 1][lr] = wa.y; Ws[lc + 2][lr] = wa.z; Ws[lc + 3][lr] = wa.w;
        Ws[lc + 0][lr + 64] = wb.x; Ws[lc + 1][lr + 64] = wb.y; Ws[lc + 2][lr + 64] = wb.z; Ws[lc + 3][lr + 64] = wb.w;
        __syncthreads();
#pragma unroll
        for (int kk = 0; kk < 16; ++kk) {
            float a[8], br[8];
            *(float4*)(a)     = *(const float4*)&Xs[kk][ty * 8];
            *(float4*)(a + 4) = *(const float4*)&Xs[kk][ty * 8 + 4];
            *(float4*)(br)     = *(const float4*)&Ws[kk][tx * 8];
            *(float4*)(br + 4) = *(const float4*)&Ws[kk][tx * 8 + 4];
#pragma unroll
            for (int i = 0; i < 8; ++i)
#pragma unroll
                for (int jj = 0; jj < 8; ++jj)
                    acc[i][jj] = fmaf(a[i], br[jj], acc[i][jj]);
        }
    }
    float bj[8];
#pragma unroll
    for (int jj = 0; jj < 8; ++jj) bj[jj] = bias ? bias[col0 + tx * 8 + jj] : 0.f;
#pragma unroll
    for (int i = 0; i < 8; ++i) {
        long row = row0 + ty * 8 + i;
        float o[8];
#pragma unroll
        for (int jj = 0; jj < 8; ++jj) {
            float v = acc[i][jj] + bj[jj];
            if (act) v = 1.f / (1.f + expf(-v));
            o[jj] = v;
        }
        *(float4*)&C[row * N + col0 + tx * 8]     = make_float4(o[0], o[1], o[2], o[3]);
        *(float4*)&C[row * N + col0 + tx * 8 + 4] = make_float4(o[4], o[5], o[6], o[7]);
    }
}

// Fused launch for the two independent consumers of inp (Wg->gate sigmoid,
// Bm->bm linear): blockIdx.z selects, halving wave-quantization tail.
__global__ __launch_bounds__(256, 2) void gemm_nt_dual(const float* __restrict__ X,
                                                        const float* __restrict__ W0,
                                                        const float* __restrict__ b0,
                                                        float* __restrict__ C0,
                                                        const float* __restrict__ W1,
                                                        float* __restrict__ C1,
                                                        int M, int N, int K) {
    const float* W  = blockIdx.z ? W1 : W0;
    const float* bs = blockIdx.z ? (const float*)0 : b0;
    float* C        = blockIdx.z ? C1 : C0;
    const int act   = blockIdx.z ? 0 : 1;
    __shared__ float Xs[16][132];
    __shared__ float Ws[16][132];
    const int tid = threadIdx.x;
    const int row0 = blockIdx.y * 128;
    const int col0 = blockIdx.x * 128;
    const int tx = tid & 15, ty = tid >> 4;
    const int lr = tid >> 2, lc = (tid & 3) << 2;
    const float* Xp = X + (long)(row0 + lr) * K + lc;
    const float* Wp = W + (long)(col0 + lr) * K + lc;
    float acc[8][8] = {};
    for (int k0 = 0; k0 < K; k0 += 16) {
        float4 xa = *(const float4*)(Xp + k0);
        float4 xb = *(const float4*)(Xp + 64L * K + k0);
        float4 wa = *(const float4*)(Wp + k0);
        float4 wb = *(const float4*)(Wp + 64L * K + k0);
        __syncthreads();
        Xs[lc + 0][lr] = xa.x; Xs[lc + 1][lr] = xa.y; Xs[lc + 2][lr] = xa.z; Xs[lc + 3][lr] = xa.w;
        Xs[lc + 0][lr + 64] = xb.x; Xs[lc + 1][lr + 64] = xb.y; Xs[lc + 2][lr + 64] = xb.z; Xs[lc + 3][lr + 64] = xb.w;
        Ws[lc + 0][lr] = wa.x; Ws[lc + 1][lr] = wa.y; Ws[lc + 2][lr] = wa.z; Ws[lc + 3][lr] = wa.w;
        Ws[lc + 0][lr + 64] = wb.x; Ws[lc + 1][lr + 64] = wb.y; Ws[lc + 2][lr + 64] = wb.z; Ws[lc + 3][lr + 64] = wb.w;
        __syncthreads();
#pragma unroll
        for (int kk = 0; kk < 16; ++kk) {
            float a[8], br[8];
            *(float4*)(a)     = *(const float4*)&Xs[kk][ty * 8];
            *(float4*)(a + 4) = *(const float4*)&Xs[kk][ty * 8 + 4];
            *(float4*)(br)     = *(const float4*)&Ws[kk][tx * 8];
            *(float4*)(br + 4) = *(const float4*)&Ws[kk][tx * 8 + 4];
#pragma unroll
            for (int i = 0; i < 8; ++i)
#pragma unroll
                for (int jj = 0; jj < 8; ++jj)
                    acc[i][jj] = fmaf(a[i], br[jj], acc[i][jj]);
        }
    }
    float bj[8];
#pragma unroll
    for (int jj = 0; jj < 8; ++jj) bj[jj] = bs ? bs[col0 + tx * 8 + jj] : 0.f;
#pragma unroll
    for (int i = 0; i < 8; ++i) {
        long row = row0 + ty * 8 + i;
        float o[8];
#pragma unroll
        for (int jj = 0; jj < 8; ++jj) {
            float v = acc[i][jj] + bj[jj];
            if (act) v = 1.f / (1.f + expf(-v));
            o[jj] = v;
        }
        *(float4*)&C[row * N + col0 + tx * 8]     = make_float4(o[0], o[1], o[2], o[3]);
        *(float4*)&C[row * N + col0 + tx * 8 + 4] = make_float4(o[4], o[5], o[6], o[7]);
    }
}

// ---------------- persistent sequential scan (the A GEMM recurrence) --------
// R8 protocol (proven): light tag poll (16 acquire loads/warp), single payload
// fetch, A slice in registers, FFMA2 GEMV + shfl butterfly. This round: fast
// tanh on the critical path; g_states store offloaded to warp 1.
__global__ __launch_bounds__(TPB, 1) void scan_kernel(const float* __restrict__ A) {
    __shared__ float bl[4 * 1028];          // blended, 4 batches x 1028 (padded)
    __shared__ float part[2][256];          // parity-split warp partials
    const int tid = threadIdx.x, w = tid >> 5, lane = tid & 31;
    const int cta = blockIdx.x;
    const int c0 = cta * 8;
    const int j = lane >> 2, q = lane & 3, b = lane & 3;
    const int colg = c0 + j;
    const int slot = b * 8 + j;             // position in payload line

    // A slice -> registers (once)
    ull a2[16];
    {
        const float* Arow = A + (long)(c0 + j) * DQ + 128 * w + 4 * q;
#pragma unroll
        for (int i = 0; i < 8; ++i) {
            float4 t = *(const float4*)(Arow + 16 * i);
            a2[2 * i]     = ((const ull*)&t)[0];
            a2[2 * i + 1] = ((const ull*)&t)[1];
        }
    }

    float st = 0.f, gv = 0.f, iv = 0.f, mv = 0.f, gv_n = 0.f, iv_n = 0.f, mv_n = 0.f;
    unsigned* mytag = &g_tag[cta][0];
    if (w <= 1) {                           // both warp0 (publish) & warp1 (store)
        long off = (long)(b * SQ) * DQ + colg;
        mv = g_bm[off];
        if (SQ > 1) mv_n = g_bm[((long)b * SQ + 1) * DQ + colg];
    }
    if (w == 0) {
        long off = (long)(b * SQ) * DQ + colg;
        gv = g_gate[off]; iv = g_inp[off];
        if (SQ > 1) {
            long off1 = ((long)b * SQ + 1) * DQ + colg;
            gv_n = g_gate[off1]; iv_n = g_inp[off1];
        }
        // preamble: publish blend_0 (st = 0), tag := 1
        float blv = fmaf(gv, st - iv, iv);
        g_pay[0][cta][slot] = blv;
        __syncwarp();
        if (lane == 0)
            asm volatile("st.release.gpu.u32 [%0], %1;" :: "l"(mytag), "r"(1u) : "memory");
    }
    __syncthreads();

    const unsigned* wtag = &g_tag[16 * w + (lane & 15)][0];

    for (int t = 0; t < SQ; ++t) {
        const int p = t & 1;
        const unsigned tgt = (unsigned)(t + 1);
        // ---- poll this warp's 16 source tags (acquire) ----
        bool ok;
        do {
            unsigned v = tgt;
            if (lane < 16)
                asm volatile("ld.acquire.gpu.u32 %0, [%1];" : "=r"(v) : "l"(wtag) : "memory");
            ok = __all_sync(0xffffffffu, v >= tgt);
        } while (!ok);

        // ---- fetch 2KB payload for this warp's 16 sources, stage into bl ----
#pragma unroll
        for (int i = 0; i < 4; ++i) {
            int idx = lane * 4 + i;
            int s_local = idx >> 3, bb = (idx >> 1) & 3, half = idx & 1;
            float4 x = *(const float4*)&g_pay[p][16 * w + s_local][bb * 8 + half * 4];
            *(float4*)(bl + bb * 1028 + (16 * w + s_local) * 8 + half * 4) = x;
        }
        __syncwarp();

        // ---- GEMV: A from regs, bl from SMEM (broadcast, conflict-free) ----
        float accb[4];
        const float* blw = bl + 128 * w + 4 * q;
#pragma unroll
        for (int b2 = 0; b2 < 4; ++b2) {
            ull acc0 = 0ull, acc1 = 0ull;
            const float* bp = blw + b2 * 1028;
#pragma unroll
            for (int i = 0; i < 8; ++i) {
                const ull* bp2 = (const ull*)(bp + 16 * i);
                acc0 = ffma2(a2[2 * i],     bp2[0], acc0);
                acc1 = ffma2(a2[2 * i + 1], bp2[1], acc1);
            }
            float l0, h0, l1, h1;
            unpack2(acc0, l0, h0);
            unpack2(acc1, l1, h1);
            accb[b2] = (l0 + h0) + (l1 + h1);
        }
        // butterfly over q bits: lane ends with the sum for batch b = q
        {
            float s0 = (q & 1) ? accb[0] : accb[1];
            float s2 = (q & 1) ? accb[2] : accb[3];
            float t0 = __shfl_xor_sync(0xffffffffu, s0, 1);
            float t2 = __shfl_xor_sync(0xffffffffu, s2, 1);
            float u0 = ((q & 1) ? accb[1] : accb[0]) + t0;  // b = q&1
            float u2 = ((q & 1) ? accb[3] : accb[2]) + t2;  // b = (q&1)+2
            float s  = (q & 2) ? u0 : u2;
            float r  = __shfl_xor_sync(0xffffffffu, s, 2);
            part[p][w * 32 + lane] = ((q & 2) ? u2 : u0) + r;
        }
        __syncthreads();

        // ---- reduce + tanh; warp0 publishes, warp1 stores g_states ----
        if (w <= 1) {
            float ssum = 0.f;
#pragma unroll
            for (int q8 = 0; q8 < 8; ++q8) ssum += part[p][q8 * 32 + lane];
            st = tanh_fast(ssum + mv);
            mv = mv_n;
            if (w == 0) {
                gv = gv_n; iv = iv_n;
                if (t + 1 < SQ) {
                    float blv = fmaf(gv, st - iv, iv);
                    g_pay[(t + 1) & 1][cta][slot] = blv;
                    __syncwarp();
                    if (lane == 0)
                        asm volatile("st.release.gpu.u32 [%0], %1;"
                                     :: "l"(mytag), "r"((unsigned)(t + 2)) : "memory");
                }
                if (t + 2 < SQ) {
                    long off = ((long)b * SQ + (t + 2)) * DQ + colg;
                    gv_n = g_gate[off]; iv_n = g_inp[off]; mv_n = g_bm[off];
                }
            } else {
                g_states[((long)b * SQ + t) * DQ + colg] = st;
                if (t + 2 < SQ)
                    mv_n = g_bm[((long)b * SQ + (t + 2)) * DQ + colg];
            }
        }
    }
}

// ---------------- launch ----------------------------------------------------
extern "C" void kernel_launch(void* const* d_in, const int* in_sizes, int n_in,
                              void* d_out, int out_size) {
    const float* q     = (const float*)d_in[0];
    const float* k     = (const float*)d_in[1];
    const float* v     = (const float*)d_in[2];
    const float* Wi    = (const float*)d_in[3];
    const float* bi    = (const float*)d_in[4];
    const float* Wg    = (const float*)d_in[5];
    const float* bg    = (const float*)d_in[6];
    const float* A     = (const float*)d_in[7];
    const float* Bm    = (const float*)d_in[8];
    const float* Wo    = (const float*)d_in[9];
    const float* bo    = (const float*)d_in[10];
    const float* decay = (const float*)d_in[11];
    float* out = (float*)d_out;

    float *retained, *inp, *gate, *bm, *states;
    cudaGetSymbolAddress((void**)&retained, g_retained);
    cudaGetSymbolAddress((void**)&inp, g_inp);
    cudaGetSymbolAddress((void**)&gate, g_gate);
    cudaGetSymbolAddress((void**)&bm, g_bm);
    cudaGetSymbolAddress((void**)&states, g_states);

    // 1) retention prefix scan -> retained
    ret_pass1<<<(NCH * BQ * DQ) / TPB, TPB>>>(k, v, decay);
    ret_pass2<<<(BQ * DQ) / TPB, TPB>>>(decay);
    ret_pass3<<<(NCH * BQ * DQ) / TPB, TPB>>>(q, k, v, decay);

    // 2) parallel big GEMMs
    dim3 gg(DQ / 128, MROWS / 128);
    gemm_nt<<<gg, 256>>>(retained, Wi, bi, inp, MROWS, DQ, DQ, 0);
    dim3 gg2(DQ / 128, MROWS / 128, 2);
    gemm_nt_dual<<<gg2, 256>>>(inp, Wg, bg, gate, Bm, bm, MROWS, DQ, DQ);

    // 3) sequential state recurrence (R8 mailbox protocol)
    reset_bar<<<NCTA, 32>>>();
    scan_kernel<<<NCTA, TPB>>>(A);

    // 4) output projection
    gemm_nt<<<gg, 256>>>(states, Wo, bo, out, MROWS, DQ, DQ, 0);
}